// round 3
// baseline (speedup 1.0000x reference)
#include <cuda_runtime.h>
#include <cstdint>

#define TT   1024
#define BB   128
#define VV   512
#define LMAX 128
#define SS   (2*LMAX + 1)   // 257
#define NEGF (-1e9f)

// Scratch (device globals — no allocation allowed)
__device__ float g_lpl[(size_t)TT * BB * LMAX];  // 64 MB: logp at label classes, dense [row][j]
__device__ float g_lpb[TT * BB];                 // logp at blank, per row
__device__ float g_ps[BB];                       // per-sample loss

__device__ __forceinline__ float lae(float x, float y) {
    // logaddexp, tolerant of NEGF sentinels
    float m = fmaxf(x, y);
    float d = fminf(x, y) - m;           // <= 0 (0 if equal)
    return m + __logf(1.0f + __expf(d));
}

// ---------------------------------------------------------------------------
// Kernel 1: per (t,b) row: log-softmax stats + dense gather of label logprobs.
// One warp per row. Row stays L1-hot for the gathers.
// ---------------------------------------------------------------------------
__global__ void k_logprobs(const float* __restrict__ acts,
                           const int*   __restrict__ labels) {
    int gw   = (blockIdx.x * blockDim.x + threadIdx.x) >> 5;   // row id = t*BB + b
    int lane = threadIdx.x & 31;
    if (gw >= TT * BB) return;

    const float* row = acts + (size_t)gw * VV;
    const float4* r4 = (const float4*)row;

    float4 a0 = r4[lane];
    float4 a1 = r4[lane + 32];
    float4 a2 = r4[lane + 64];
    float4 a3 = r4[lane + 96];

    float m = fmaxf(fmaxf(fmaxf(a0.x, a0.y), fmaxf(a0.z, a0.w)),
                    fmaxf(fmaxf(a1.x, a1.y), fmaxf(a1.z, a1.w)));
    m = fmaxf(m, fmaxf(fmaxf(a2.x, a2.y), fmaxf(a2.z, a2.w)));
    m = fmaxf(m, fmaxf(fmaxf(a3.x, a3.y), fmaxf(a3.z, a3.w)));
    #pragma unroll
    for (int o = 16; o; o >>= 1) m = fmaxf(m, __shfl_xor_sync(0xFFFFFFFFu, m, o));

    float s = __expf(a0.x - m) + __expf(a0.y - m) + __expf(a0.z - m) + __expf(a0.w - m)
            + __expf(a1.x - m) + __expf(a1.y - m) + __expf(a1.z - m) + __expf(a1.w - m)
            + __expf(a2.x - m) + __expf(a2.y - m) + __expf(a2.z - m) + __expf(a2.w - m)
            + __expf(a3.x - m) + __expf(a3.y - m) + __expf(a3.z - m) + __expf(a3.w - m);
    #pragma unroll
    for (int o = 16; o; o >>= 1) s += __shfl_xor_sync(0xFFFFFFFFu, s, o);

    float lse = m + __logf(s);

    int b = gw & (BB - 1);
    const int* lab = labels + b * LMAX;
    float* dst = g_lpl + (size_t)gw * LMAX;
    #pragma unroll
    for (int j = lane; j < LMAX; j += 32) {
        int c = lab[j];                 // in [1, VV)
        dst[j] = row[c] - lse;          // L1 hit (row just streamed through)
    }
    if (lane == 0) g_lpb[gw] = row[0] - lse;
}

// ---------------------------------------------------------------------------
// Kernel 2: per-sample alpha scan. One CTA per batch element, 288 threads,
// thread s owns extended position s (s < 257). Double-buffered smem alpha,
// one barrier per step, t+1 log-prob prefetched into registers.
// ---------------------------------------------------------------------------
__global__ __launch_bounds__(288, 1)
void k_alpha(const int* __restrict__ labels,
             const int* __restrict__ act_lens,
             const int* __restrict__ label_lens) {
    __shared__ float alpha[2][SS];
    __shared__ int   lab[LMAX];

    int b   = blockIdx.x;
    int tid = threadIdx.x;

    if (tid < LMAX) lab[tid] = labels[b * LMAX + tid];
    __syncthreads();

    int  s      = tid;
    bool active = (s < SS);
    bool odd    = (s & 1) != 0;
    int  j      = s >> 1;                       // label index for odd s
    bool allow2 = active && odd && (s >= 3) && (lab[j] != lab[j - 1]);
    int  len    = act_lens[b];

    // Per-thread streaming pointer for its log-prob sequence:
    //   odd  s: g_lpl[(t*BB + b)*LMAX + j], stride BB*LMAX floats per t
    //   even s: g_lpb[t*BB + b],            stride BB floats per t
    const float* lp_ptr  = odd ? (g_lpl + ((size_t)BB + b) * LMAX + j)   // t = 1
                               : (g_lpb + BB + b);
    const long   lp_strd = odd ? (long)BB * LMAX : (long)BB;

    // t = 0 init
    if (active) {
        float a0 = NEGF;
        if (s == 0) a0 = g_lpb[b];                       // row 0*BB + b
        else if (s == 1) a0 = g_lpl[(size_t)b * LMAX];   // j = 0
        alpha[0][s] = a0;
    }
    __syncthreads();

    // prefetch t = 1
    float nlp = 0.0f;
    if (active) nlp = *lp_ptr;
    lp_ptr += lp_strd;

    int cur = 0;
    for (int t = 1; t < len; t++) {
        float lp = nlp;
        if (active && t + 1 < len) nlp = *lp_ptr;        // prefetch t+1
        lp_ptr += lp_strd;

        int nxt = cur ^ 1;
        if (active) {
            float a  = alpha[cur][s];
            float p1 = (s >= 1) ? alpha[cur][s - 1] : NEGF;
            a = lae(a, p1);
            if (allow2) a = lae(a, alpha[cur][s - 2]);
            alpha[nxt][s] = a + lp;
        }
        __syncthreads();
        cur = nxt;
    }

    if (tid == 0) {
        int end = 2 * label_lens[b];            // in [128, 256]
        g_ps[b] = -lae(alpha[cur][end], alpha[cur][end - 1]);
    }
}

// ---------------------------------------------------------------------------
// Kernel 3: deterministic mean over B=128 per-sample losses.
// ---------------------------------------------------------------------------
__global__ void k_final(float* __restrict__ out) {
    __shared__ float sh[4];
    int tid = threadIdx.x;                     // 128 threads
    float v = g_ps[tid];
    #pragma unroll
    for (int o = 16; o; o >>= 1) v += __shfl_xor_sync(0xFFFFFFFFu, v, o);
    if ((tid & 31) == 0) sh[tid >> 5] = v;
    __syncthreads();
    if (tid == 0) out[0] = (sh[0] + sh[1] + sh[2] + sh[3]) * (1.0f / (float)BB);
}

extern "C" void kernel_launch(void* const* d_in, const int* in_sizes, int n_in,
                              void* d_out, int out_size) {
    const float* acts       = (const float*)d_in[0];
    const int*   labels     = (const int*)d_in[1];
    const int*   act_lens   = (const int*)d_in[2];
    const int*   label_lens = (const int*)d_in[3];
    (void)in_sizes; (void)n_in; (void)out_size;

    k_logprobs<<<(TT * BB) / 8, 256>>>(acts, labels);
    k_alpha<<<BB, 288>>>(labels, act_lens, label_lens);
    k_final<<<1, 128>>>((float*)d_out);
}

// round 4
// speedup vs baseline: 2.4180x; 2.4180x over previous
#include <cuda_runtime.h>
#include <cstdint>

#define TT    1024
#define BB    128
#define VV    512
#define LMAX  128
#define SS    (2*LMAX + 1)   // 257
#define NEGF  (-1e9f)
#define ROWW  132            // floats per (b,t) row: [blank, lab0..lab127, pad x3]
#define CHUNK 16             // timesteps per cp.async tile

// Scratch (device globals — no allocation allowed)
__device__ __align__(16) float g_lp[(size_t)BB * TT * ROWW];  // ~69 MB, [b][t][ROWW]
__device__ float g_ps[BB];

__device__ __forceinline__ float lae2(float x, float y) {
    float m = fmaxf(x, y);
    return m + __logf(__expf(x - m) + __expf(y - m));
}
__device__ __forceinline__ float lae3(float x, float y, float z) {
    float m = fmaxf(fmaxf(x, y), z);
    return m + __logf(__expf(x - m) + __expf(y - m) + __expf(z - m));
}

__device__ __forceinline__ void cpasync16(void* smem_dst, const void* gsrc) {
    uint32_t sa = (uint32_t)__cvta_generic_to_shared(smem_dst);
    asm volatile("cp.async.cg.shared.global [%0], [%1], 16;\n" :: "r"(sa), "l"(gsrc));
}

// ---------------------------------------------------------------------------
// Kernel 1: per (t,b) row: log-softmax + dense gather of label logprobs into
// per-sample-contiguous layout g_lp[b][t][...]. One warp per row.
// ---------------------------------------------------------------------------
__global__ void k_logprobs(const float* __restrict__ acts,
                           const int*   __restrict__ labels) {
    int gw   = (blockIdx.x * blockDim.x + threadIdx.x) >> 5;   // row id = t*BB + b
    int lane = threadIdx.x & 31;
    if (gw >= TT * BB) return;

    const float* row = acts + (size_t)gw * VV;
    const float4* r4 = (const float4*)row;

    float4 a0 = r4[lane];
    float4 a1 = r4[lane + 32];
    float4 a2 = r4[lane + 64];
    float4 a3 = r4[lane + 96];

    float m = fmaxf(fmaxf(fmaxf(a0.x, a0.y), fmaxf(a0.z, a0.w)),
                    fmaxf(fmaxf(a1.x, a1.y), fmaxf(a1.z, a1.w)));
    m = fmaxf(m, fmaxf(fmaxf(a2.x, a2.y), fmaxf(a2.z, a2.w)));
    m = fmaxf(m, fmaxf(fmaxf(a3.x, a3.y), fmaxf(a3.z, a3.w)));
    #pragma unroll
    for (int o = 16; o; o >>= 1) m = fmaxf(m, __shfl_xor_sync(0xFFFFFFFFu, m, o));

    float s = __expf(a0.x - m) + __expf(a0.y - m) + __expf(a0.z - m) + __expf(a0.w - m)
            + __expf(a1.x - m) + __expf(a1.y - m) + __expf(a1.z - m) + __expf(a1.w - m)
            + __expf(a2.x - m) + __expf(a2.y - m) + __expf(a2.z - m) + __expf(a2.w - m)
            + __expf(a3.x - m) + __expf(a3.y - m) + __expf(a3.z - m) + __expf(a3.w - m);
    #pragma unroll
    for (int o = 16; o; o >>= 1) s += __shfl_xor_sync(0xFFFFFFFFu, s, o);

    float lse = m + __logf(s);

    int b = gw & (BB - 1);
    int t = gw >> 7;                    // gw / BB
    const int* lab = labels + b * LMAX;
    float* dst = g_lp + ((size_t)b * TT + t) * ROWW;
    #pragma unroll
    for (int j = lane; j < LMAX; j += 32) {
        int c = lab[j];                 // in [1, VV)
        dst[1 + j] = row[c] - lse;      // L1 hit (row just streamed)
    }
    if (lane == 0) dst[0] = row[0] - lse;   // blank
}

// ---------------------------------------------------------------------------
// Kernel 2: per-sample alpha scan. 288 threads:
//   tid 0..128   -> even s = 2*i  (blank positions, 2-term logaddexp)
//   tid 160..287 -> odd  s = 2*i+1 (label positions, 3-term logaddexp)
// Log-probs streamed through double-buffered cp.async tiles of CHUNK steps.
// ---------------------------------------------------------------------------
__global__ __launch_bounds__(288, 1)
void k_alpha(const int* __restrict__ labels,
             const int* __restrict__ act_lens,
             const int* __restrict__ label_lens) {
    __shared__ __align__(16) float tile[2][CHUNK][ROWW];  // 16.5 KB
    __shared__ float ae[2][132];      // even-s alpha, i = 0..128
    __shared__ float ao[2][132];      // odd-s alpha,  i = 0..127
    __shared__ int   lab[LMAX];

    int b   = blockIdx.x;
    int tid = threadIdx.x;

    if (tid < LMAX) lab[tid] = labels[b * LMAX + tid];
    __syncthreads();

    bool isEven = (tid < 129);
    bool isOdd  = (tid >= 160);
    int  i      = isEven ? tid : (tid - 160);
    bool allow2 = isOdd && (i >= 1) && (lab[i] != lab[i - 1]);
    int  len    = act_lens[b];

    const float* my = g_lp + (size_t)b * TT * ROWW;

    // t = 0 init: alpha[0] = lp_blank(0), alpha[1] = lp_lab0(0), rest NEG
    if (isEven) ae[0][i] = (i == 0) ? my[0] : NEGF;
    if (isOdd)  ao[0][i] = (i == 0) ? my[1] : NEGF;

    // ---- cp.async chunk prefetcher ----
    const int NW = CHUNK * (ROWW / 4);      // 16-byte words per chunk = 528
    auto prefetch = [&](int t0, int bf) {
        for (int w = tid; w < NW; w += 288) {
            int tt = w / (ROWW / 4);
            int q  = w - tt * (ROWW / 4);
            int t  = t0 + tt;
            if (t < TT)
                cpasync16(&tile[bf][tt][q * 4],
                          my + (size_t)t * ROWW + q * 4);
        }
        asm volatile("cp.async.commit_group;\n");
    };

    prefetch(1, 0);                          // chunk 0
    if (1 + CHUNK < len) prefetch(1 + CHUNK, 1);  // chunk 1

    int cur = 0;
    int buf = 0;
    for (int base = 1; base < len; base += CHUNK, buf ^= 1) {
        // wait for this chunk (one more group may be in flight behind it)
        if (base + CHUNK < len) asm volatile("cp.async.wait_group 1;\n");
        else                    asm volatile("cp.async.wait_group 0;\n");
        __syncthreads();

        int hi = (base + CHUNK < len) ? (base + CHUNK) : len;
        for (int t = base; t < hi; t++) {
            int tt  = t - base;
            int nxt = cur ^ 1;
            if (isEven) {
                float lp = tile[buf][tt][0];
                float x  = ae[cur][i];
                float y  = (i >= 1) ? ao[cur][i - 1] : NEGF;
                ae[nxt][i] = lae2(x, y) + lp;
            }
            if (isOdd) {
                float lp = tile[buf][tt][1 + i];
                float x  = ao[cur][i];
                float y  = ae[cur][i];
                float z  = allow2 ? ao[cur][i - 1] : NEGF;
                ao[nxt][i] = lae3(x, y, z) + lp;
            }
            __syncthreads();
            cur = nxt;
        }

        // queue chunk base + 2*CHUNK into the buffer just consumed
        int nb = base + 2 * CHUNK;
        if (nb < len) prefetch(nb, buf);
    }

    if (tid == 0) {
        int end = 2 * label_lens[b];         // even s, >= 128
        float x = ae[cur][end >> 1];
        float y = ao[cur][(end >> 1) - 1];   // s = end-1 (odd)
        g_ps[b] = -lae2(x, y);
    }
}

// ---------------------------------------------------------------------------
// Kernel 3: deterministic mean over B=128 per-sample losses.
// ---------------------------------------------------------------------------
__global__ void k_final(float* __restrict__ out) {
    __shared__ float sh[4];
    int tid = threadIdx.x;                   // 128 threads
    float v = g_ps[tid];
    #pragma unroll
    for (int o = 16; o; o >>= 1) v += __shfl_xor_sync(0xFFFFFFFFu, v, o);
    if ((tid & 31) == 0) sh[tid >> 5] = v;
    __syncthreads();
    if (tid == 0) out[0] = (sh[0] + sh[1] + sh[2] + sh[3]) * (1.0f / (float)BB);
}

extern "C" void kernel_launch(void* const* d_in, const int* in_sizes, int n_in,
                              void* d_out, int out_size) {
    const float* acts       = (const float*)d_in[0];
    const int*   labels     = (const int*)d_in[1];
    const int*   act_lens   = (const int*)d_in[2];
    const int*   label_lens = (const int*)d_in[3];
    (void)in_sizes; (void)n_in; (void)out_size;

    k_logprobs<<<(TT * BB) / 8, 256>>>(acts, labels);
    k_alpha<<<BB, 288>>>(labels, act_lens, label_lens);
    k_final<<<1, 128>>>((float*)d_out);
}

// round 5
// speedup vs baseline: 2.6602x; 1.1002x over previous
#include <cuda_runtime.h>
#include <cstdint>

#define TT    1024
#define BB    128
#define VV    512
#define LMAX  128
#define NEGF  (-1e9f)
#define ROWW  132            // floats per (b,t) row: [blank, lab0..lab127, pad x3]
#define CHUNK 24             // timesteps per cp.async tile (multiple of KSTEP)
#define KSTEP 6              // steps per barrier phase (wavefront halo depth)
#define PWARP 26             // owned pairs per warp (32 - KSTEP)
#define NTHR  160            // 5 warps

// Scratch (device globals — no allocation allowed)
__device__ __align__(16) float g_lp[(size_t)BB * TT * ROWW];  // ~69 MB, [b][t][ROWW]
__device__ float g_ps[BB];

__device__ __forceinline__ float lae2(float x, float y) {
    float m = fmaxf(x, y);
    float d = fminf(x, y) - m;                 // <= 0
    return m + __logf(1.0f + __expf(d));
}
__device__ __forceinline__ float lae3(float x, float y, float z) {
    float m = fmaxf(fmaxf(x, y), z);
    return m + __logf(__expf(x - m) + __expf(y - m) + __expf(z - m));
}

__device__ __forceinline__ void cpasync16(void* smem_dst, const void* gsrc) {
    uint32_t sa = (uint32_t)__cvta_generic_to_shared(smem_dst);
    asm volatile("cp.async.cg.shared.global [%0], [%1], 16;\n" :: "r"(sa), "l"(gsrc));
}

// ---------------------------------------------------------------------------
// Kernel 1: per (t,b) row: log-softmax + dense gather of label logprobs into
// per-sample-contiguous layout g_lp[b][t][...]. One warp per row.
// ---------------------------------------------------------------------------
__global__ void k_logprobs(const float* __restrict__ acts,
                           const int*   __restrict__ labels) {
    int gw   = (blockIdx.x * blockDim.x + threadIdx.x) >> 5;   // row id = t*BB + b
    int lane = threadIdx.x & 31;
    if (gw >= TT * BB) return;

    const float* row = acts + (size_t)gw * VV;
    const float4* r4 = (const float4*)row;

    float4 a0 = r4[lane];
    float4 a1 = r4[lane + 32];
    float4 a2 = r4[lane + 64];
    float4 a3 = r4[lane + 96];

    float m = fmaxf(fmaxf(fmaxf(a0.x, a0.y), fmaxf(a0.z, a0.w)),
                    fmaxf(fmaxf(a1.x, a1.y), fmaxf(a1.z, a1.w)));
    m = fmaxf(m, fmaxf(fmaxf(a2.x, a2.y), fmaxf(a2.z, a2.w)));
    m = fmaxf(m, fmaxf(fmaxf(a3.x, a3.y), fmaxf(a3.z, a3.w)));
    #pragma unroll
    for (int o = 16; o; o >>= 1) m = fmaxf(m, __shfl_xor_sync(0xFFFFFFFFu, m, o));

    float s = __expf(a0.x - m) + __expf(a0.y - m) + __expf(a0.z - m) + __expf(a0.w - m)
            + __expf(a1.x - m) + __expf(a1.y - m) + __expf(a1.z - m) + __expf(a1.w - m)
            + __expf(a2.x - m) + __expf(a2.y - m) + __expf(a2.z - m) + __expf(a2.w - m)
            + __expf(a3.x - m) + __expf(a3.y - m) + __expf(a3.z - m) + __expf(a3.w - m);
    #pragma unroll
    for (int o = 16; o; o >>= 1) s += __shfl_xor_sync(0xFFFFFFFFu, s, o);

    float lse = m + __logf(s);

    int b = gw & (BB - 1);
    int t = gw >> 7;
    const int* lab = labels + b * LMAX;
    float* dst = g_lp + ((size_t)b * TT + t) * ROWW;
    #pragma unroll
    for (int j = lane; j < LMAX; j += 32) {
        int c = lab[j];                 // in [1, VV)
        dst[1 + j] = row[c] - lse;      // L1 hit (row just streamed)
    }
    if (lane == 0) dst[0] = row[0] - lse;   // blank
}

// ---------------------------------------------------------------------------
// Kernel 2: per-sample alpha scan, wavefront-halo style. One CTA per sample,
// 160 threads (5 warps). Thread handles PAIR p = (s=2p even, s=2p+1 odd):
//   ae'[p] = lae2(ae[p], ao[p-1]) + lp_blank
//   ao'[p] = lae3(ao[p], ae[p], ao[p-1] if allowed) + lp_label[p]
// Only cross-thread dep is ao[p-1] -> one __shfl_up per step, NO barrier.
// Warp w covers p = PWARP*w - KSTEP + lane; lanes 0..KSTEP-1 are decaying
// halo (recompute left warp's pairs), lanes >= KSTEP own PWARP pairs.
// One smem exchange + one __syncthreads per KSTEP steps.
// Log-probs streamed via double-buffered cp.async tiles of CHUNK steps.
// ---------------------------------------------------------------------------
__global__ __launch_bounds__(NTHR, 1)
void k_alpha(const int* __restrict__ labels,
             const int* __restrict__ act_lens,
             const int* __restrict__ label_lens) {
    __shared__ __align__(16) float tile[2][CHUNK][ROWW];  // 25.3 KB
    __shared__ float xae[2][132];     // pair-exchange, even-s alpha (p=0..128)
    __shared__ float xao[2][132];     // pair-exchange, odd-s alpha  (p=0..127)
    __shared__ int   lab[LMAX];

    int b   = blockIdx.x;
    int tid = threadIdx.x;
    int w   = tid >> 5;
    int l   = tid & 31;
    int p   = PWARP * w - KSTEP + l;          // pair index in [-6, 129]

    if (tid < LMAX) lab[tid] = labels[b * LMAX + tid];
    if (tid < 132) { xae[0][tid] = NEGF; xao[0][tid] = NEGF; }
    int len = act_lens[b];
    const float* my = g_lp + (size_t)b * TT * ROWW;
    __syncthreads();
    if (tid == 0) { xae[0][0] = my[0]; xao[0][0] = my[1]; }   // t=0 init

    bool haveP  = (p >= 0 && p <= 128);
    bool haveO  = (p >= 0 && p <= 127);
    bool ownA   = (l >= KSTEP) && (p <= 128);
    bool ownO   = (l >= KSTEP) && (p <= 127);
    bool allow2 = (p >= 1 && p <= 127) ? (lab[p] != lab[p - 1]) : false;

    // ---- cp.async chunk prefetcher ----
    const int NW = CHUNK * (ROWW / 4);        // 792 16B words per chunk
    auto prefetch = [&](int t0, int bf) {
        for (int wd = tid; wd < NW; wd += NTHR) {
            int tt = wd / (ROWW / 4);
            int q  = wd - tt * (ROWW / 4);
            int t  = t0 + tt;
            if (t < TT)
                cpasync16(&tile[bf][tt][q * 4], my + (size_t)t * ROWW + q * 4);
        }
        asm volatile("cp.async.commit_group;\n");
    };

    prefetch(1, 0);
    if (1 + CHUNK < len) prefetch(1 + CHUNK, 1);
    __syncthreads();   // t=0 init + lab visible; cp.async groups committed

    int par = 0, buf = 0;
    for (int cs = 1; cs < len; cs += CHUNK, buf ^= 1) {
        bool more = (cs + CHUNK) < len;       // matches commit bookkeeping
        if (more) asm volatile("cp.async.wait_group 1;\n");
        else      asm volatile("cp.async.wait_group 0;\n");
        __syncthreads();                      // tile[buf] ready for all

        int ce = more ? (cs + CHUNK) : len;
        for (int base = cs; base < ce; base += KSTEP) {
            float a_e = haveP ? xae[par][p] : NEGF;
            float a_o = haveO ? xao[par][p] : NEGF;

            #pragma unroll
            for (int k = 0; k < KSTEP; k++) {
                if (base + k >= ce) break;    // uniform across CTA
                int tt = base + k - cs;
                float lpb = tile[buf][tt][0];
                float lpl = haveO ? tile[buf][tt][1 + p] : NEGF;
                float aim1 = __shfl_up_sync(0xFFFFFFFFu, a_o, 1);
                if (l == 0) aim1 = NEGF;
                float nae = lae2(a_e, aim1) + lpb;
                float z   = allow2 ? aim1 : NEGF;
                float nao = lae3(a_o, a_e, z) + lpl;
                a_e = nae;
                a_o = nao;
            }

            if (ownA) xae[par ^ 1][p] = a_e;
            if (ownO) xao[par ^ 1][p] = a_o;
            __syncthreads();
            par ^= 1;
        }

        int nc = cs + 2 * CHUNK;
        if (nc < len) prefetch(nc, buf);      // refill consumed buffer
    }

    if (tid == 0) {
        int L = label_lens[b];                // end = 2L -> ae[L], ao[L-1]
        g_ps[b] = -lae2(xae[par][L], xao[par][L - 1]);
    }
}

// ---------------------------------------------------------------------------
// Kernel 3: deterministic mean over B=128 per-sample losses.
// ---------------------------------------------------------------------------
__global__ void k_final(float* __restrict__ out) {
    __shared__ float sh[4];
    int tid = threadIdx.x;                    // 128 threads
    float v = g_ps[tid];
    #pragma unroll
    for (int o = 16; o; o >>= 1) v += __shfl_xor_sync(0xFFFFFFFFu, v, o);
    if ((tid & 31) == 0) sh[tid >> 5] = v;
    __syncthreads();
    if (tid == 0) out[0] = (sh[0] + sh[1] + sh[2] + sh[3]) * (1.0f / (float)BB);
}

extern "C" void kernel_launch(void* const* d_in, const int* in_sizes, int n_in,
                              void* d_out, int out_size) {
    const float* acts       = (const float*)d_in[0];
    const int*   labels     = (const int*)d_in[1];
    const int*   act_lens   = (const int*)d_in[2];
    const int*   label_lens = (const int*)d_in[3];
    (void)in_sizes; (void)n_in; (void)out_size;

    k_logprobs<<<(TT * BB) / 8, 256>>>(acts, labels);
    k_alpha<<<BB, NTHR>>>(labels, act_lens, label_lens);
    k_final<<<1, 128>>>((float*)d_out);
}

// round 12
// speedup vs baseline: 4.1565x; 1.5625x over previous
#include <cuda_runtime.h>
#include <cstdint>

#define TT    1024
#define BB    128
#define VV    512
#define LMAX  128
#define ROWW  132            // floats per (b,t) row: [u_blank, u_lab0..127, pad]
#define CHUNK 24             // timesteps per cp.async tile (multiple of KSTEP)
#define KSTEP 6              // steps per barrier phase (wavefront halo depth)
#define PWARP 26             // owned pairs per warp (32 - KSTEP)
#define NTHR  160            // 5 warps
#define NWARP 5
#define TEXP  100            // renorm target exponent: pin block max to ~2^100
#define LN2F  0.6931471805599453f

// Scratch (device globals — no allocation allowed)
__device__ __align__(16) float g_lp[(size_t)BB * TT * ROWW];  // ~69 MB, [b][t][ROWW], u-values
__device__ float g_lz[TT * BB];    // per-row log-sum-exp residual: log(sum exp(a - max))
__device__ float g_ps[BB];

__device__ __forceinline__ void cpasync16(void* smem_dst, const void* gsrc) {
    uint32_t sa = (uint32_t)__cvta_generic_to_shared(smem_dst);
    asm volatile("cp.async.cg.shared.global [%0], [%1], 16;\n" :: "r"(sa), "l"(gsrc));
}

// ---------------------------------------------------------------------------
// Kernel 1: per (t,b) row: softmax stats; store UNNORMALIZED probs
// u[c] = exp(a[c] - rowmax) for blank+labels, plus lz = log(sum exp(a-rowmax)).
// One warp per row; gathers hit L1.
// ---------------------------------------------------------------------------
__global__ void k_logprobs(const float* __restrict__ acts,
                           const int*   __restrict__ labels) {
    int gw   = (blockIdx.x * blockDim.x + threadIdx.x) >> 5;   // row id = t*BB + b
    int lane = threadIdx.x & 31;
    if (gw >= TT * BB) return;

    const float* row = acts + (size_t)gw * VV;
    const float4* r4 = (const float4*)row;

    float4 a0 = r4[lane];
    float4 a1 = r4[lane + 32];
    float4 a2 = r4[lane + 64];
    float4 a3 = r4[lane + 96];

    float m = fmaxf(fmaxf(fmaxf(a0.x, a0.y), fmaxf(a0.z, a0.w)),
                    fmaxf(fmaxf(a1.x, a1.y), fmaxf(a1.z, a1.w)));
    m = fmaxf(m, fmaxf(fmaxf(a2.x, a2.y), fmaxf(a2.z, a2.w)));
    m = fmaxf(m, fmaxf(fmaxf(a3.x, a3.y), fmaxf(a3.z, a3.w)));
    #pragma unroll
    for (int o = 16; o; o >>= 1) m = fmaxf(m, __shfl_xor_sync(0xFFFFFFFFu, m, o));

    float s = __expf(a0.x - m) + __expf(a0.y - m) + __expf(a0.z - m) + __expf(a0.w - m)
            + __expf(a1.x - m) + __expf(a1.y - m) + __expf(a1.z - m) + __expf(a1.w - m)
            + __expf(a2.x - m) + __expf(a2.y - m) + __expf(a2.z - m) + __expf(a2.w - m)
            + __expf(a3.x - m) + __expf(a3.y - m) + __expf(a3.z - m) + __expf(a3.w - m);
    #pragma unroll
    for (int o = 16; o; o >>= 1) s += __shfl_xor_sync(0xFFFFFFFFu, s, o);

    int b = gw & (BB - 1);
    int t = gw >> 7;
    const int* lab = labels + b * LMAX;
    float* dst = g_lp + ((size_t)b * TT + t) * ROWW;
    #pragma unroll
    for (int j = lane; j < LMAX; j += 32) {
        int c = lab[j];                       // in [1, VV)
        dst[1 + j] = __expf(row[c] - m);      // L1 hit
    }
    if (lane == 0) {
        dst[0] = __expf(row[0] - m);          // blank
        g_lz[gw] = __logf(s);                 // residual normalizer
    }
}

// ---------------------------------------------------------------------------
// Kernel 2: per-sample alpha scan in SCALED LINEAR domain (no MUFU in loop).
// Pair p owns s=2p (even/blank) and s=2p+1 (odd/label):
//   ae' = (ae + ao[p-1]) * u_blank
//   ao' = (ao + ae + [allow2]*ao[p-1]) * u_lab[p]
// Lattice truncated at the true label length Lb (p >= Lb identically 0).
// Wavefront halo: KSTEP barrier-free steps per phase via one shfl_up/step.
// Power-of-2 renorm once per phase pins the block max to ~2^TEXP (=2^100):
// flush floor is then 100+126 bits ~ 157 nats below the running max (vs 87
// when pinning to 2^0 — that band held real path mass and caused R11's
// 3.8e-3 error). Within-phase growth <= 3^6 < 2^10 keeps max < 2^110 < inf.
// wred double-buffered by phase parity (two-barrier separation).
// log P = log(ae_end + ao_end-1) + ln2*Ce - sum_t lz(t).
// ---------------------------------------------------------------------------
__global__ __launch_bounds__(NTHR, 1)
void k_alpha(const int* __restrict__ labels,
             const int* __restrict__ act_lens,
             const int* __restrict__ label_lens) {
    __shared__ __align__(16) float tile[2][CHUNK][ROWW];  // 25.3 KB
    __shared__ float xae[2][132];
    __shared__ float xao[2][132];
    __shared__ float wred[2][NWARP];  // renorm max, double-buffered by parity
    __shared__ int   lab[LMAX];

    int b   = blockIdx.x;
    int tid = threadIdx.x;
    int w   = tid >> 5;
    int l   = tid & 31;
    int p   = PWARP * w - KSTEP + l;          // pair index in [-6, 129]

    if (tid < LMAX) lab[tid] = labels[b * LMAX + tid];
    if (tid < 132) { xae[0][tid] = 0.0f; xao[0][tid] = 0.0f; }
    int len = act_lens[b];
    int Lb  = label_lens[b];                  // true label length, [64, 128]
    const float* my = g_lp + (size_t)b * TT * ROWW;
    __syncthreads();
    if (tid == 0) { xae[0][0] = my[0]; xao[0][0] = my[1]; }   // t=0 init (u-values)

    bool haveP  = (p >= 0 && p <= 128);
    bool okO    = (p >= 0 && p < Lb);         // active odd positions only
    bool ownA   = (l >= KSTEP) && (p >= 0) && (p <= 128);
    bool ownO   = (l >= KSTEP) && (p >= 0) && (p <= 127);
    float allow2f = ((p >= 1 && p <= 127) ? (lab[p] != lab[p - 1]) : false) ? 1.0f : 0.0f;

    // ---- cp.async chunk prefetcher ----
    const int NWD = CHUNK * (ROWW / 4);       // 16B words per chunk
    auto prefetch = [&](int t0, int bf) {
        for (int wd = tid; wd < NWD; wd += NTHR) {
            int tt = wd / (ROWW / 4);
            int q  = wd - tt * (ROWW / 4);
            int t  = t0 + tt;
            if (t < TT)
                cpasync16(&tile[bf][tt][q * 4], my + (size_t)t * ROWW + q * 4);
        }
        asm volatile("cp.async.commit_group;\n");
    };

    prefetch(1, 0);
    if (1 + CHUNK < len) prefetch(1 + CHUNK, 1);
    __syncthreads();

    int   par   = 0, buf = 0;
    int   Ce    = 0;         // accumulated renorm exponent: true = stored * 2^Ce
    int   pend  = 0;         // exponent of last phase's max (2^pend >= mx)
    float scale = __int_as_float((127 + TEXP) << 23);   // 2^(TEXP - pend), pend=0

    for (int cs = 1; cs < len; cs += CHUNK, buf ^= 1) {
        bool more = (cs + CHUNK) < len;
        if (more) asm volatile("cp.async.wait_group 1;\n");
        else      asm volatile("cp.async.wait_group 0;\n");
        __syncthreads();                      // tile[buf] ready

        int ce = more ? (cs + CHUNK) : len;
        for (int base = cs; base < ce; base += KSTEP) {
            float a_e = haveP ? xae[par][p] * scale : 0.0f;
            float a_o = okO   ? xao[par][p] * scale : 0.0f;
            Ce += pend - TEXP;               // matches scale = 2^(TEXP-pend)

            #pragma unroll
            for (int k = 0; k < KSTEP; k++) {
                if (base + k >= ce) break;    // uniform across CTA
                int tt = base + k - cs;
                float ub = tile[buf][tt][0];
                float ul = okO ? tile[buf][tt][1 + p] : 0.0f;
                float aim1 = __shfl_up_sync(0xFFFFFFFFu, a_o, 1);
                if (l == 0) aim1 = 0.0f;
                float nae = (a_e + aim1) * ub;
                float nao = (a_o + a_e + allow2f * aim1) * ul;
                a_e = nae;
                a_o = nao;
            }

            // per-warp max for renorm (halo lanes only underestimate -> safe;
            // p > Lb positions are identically 0 and cannot dominate)
            float v = fmaxf(a_e, a_o);
            #pragma unroll
            for (int o = 16; o; o >>= 1) v = fmaxf(v, __shfl_xor_sync(0xFFFFFFFFu, v, o));
            if (l == 0) wred[par][w] = v;

            if (ownA) xae[par ^ 1][p] = a_e;
            if (ownO) xao[par ^ 1][p] = a_o;
            __syncthreads();

            // uniform rescale-to-2^TEXP factor for next phase (reads the
            // parity slot just written; next write to it is 2 barriers away)
            float mx = fmaxf(fmaxf(fmaxf(wred[par][0], wred[par][1]),
                                   fmaxf(wred[par][2], wred[par][3])), wred[par][4]);
            par ^= 1;
            pend  = (__float_as_int(mx) >> 23) - 126;           // 2^pend >= mx
            scale = __int_as_float((127 + TEXP - pend) << 23);  // 2^(TEXP-pend)
        }

        int nc = cs + 2 * CHUNK;
        if (nc < len) prefetch(nc, buf);
    }

    // ---- sum of per-row normalizers lz over t < len ----
    float slz = 0.0f;
    for (int t = tid; t < len; t += NTHR) slz += g_lz[t * BB + b];
    #pragma unroll
    for (int o = 16; o; o >>= 1) slz += __shfl_xor_sync(0xFFFFFFFFu, slz, o);
    __syncthreads();
    if (l == 0) wred[0][w] = slz;
    __syncthreads();

    if (tid == 0) {
        float SLZ = wred[0][0] + wred[0][1] + wred[0][2] + wred[0][3] + wred[0][4];
        float af = xae[par][Lb] + xao[par][Lb - 1];   // end = 2L -> ae[L], ao[L-1]
        g_ps[b] = -(__logf(af) + (float)Ce * LN2F - SLZ);
    }
}

// ---------------------------------------------------------------------------
// Kernel 3: deterministic mean over B=128 per-sample losses.
// ---------------------------------------------------------------------------
__global__ void k_final(float* __restrict__ out) {
    __shared__ float sh[4];
    int tid = threadIdx.x;                   // 128 threads
    float v = g_ps[tid];
    #pragma unroll
    for (int o = 16; o; o >>= 1) v += __shfl_xor_sync(0xFFFFFFFFu, v, o);
    if ((tid & 31) == 0) sh[tid >> 5] = v;
    __syncthreads();
    if (tid == 0) out[0] = (sh[0] + sh[1] + sh[2] + sh[3]) * (1.0f / (float)BB);
}

extern "C" void kernel_launch(void* const* d_in, const int* in_sizes, int n_in,
                              void* d_out, int out_size) {
    const float* acts       = (const float*)d_in[0];
    const int*   labels     = (const int*)d_in[1];
    const int*   act_lens   = (const int*)d_in[2];
    const int*   label_lens = (const int*)d_in[3];
    (void)in_sizes; (void)n_in; (void)out_size;

    k_logprobs<<<(TT * BB) / 8, 256>>>(acts, labels);
    k_alpha<<<BB, NTHR>>>(labels, act_lens, label_lens);
    k_final<<<1, 128>>>((float*)d_out);
}

// round 13
// speedup vs baseline: 5.4185x; 1.3036x over previous
#include <cuda_runtime.h>
#include <cuda_fp16.h>
#include <cstdint>

#define TT    1024
#define BB    128
#define VV    512
#define LMAX  128
#define ROWH  136            // halves per (b,t) row: [u_blank, u_lab0..127, pad] (272B = 17*16)
#define CHUNK 24             // timesteps per cp.async tile (2 phases)
#define KSTEP 12             // steps per barrier phase (wavefront halo depth)
#define PWARP 20             // owned pairs per warp (32 - KSTEP)
#define NTHR  224            // 7 warps
#define NWARP 7
#define TEXP  100            // renorm target exponent: pin block max to ~2^100
#define LN2F  0.6931471805599453f

// Scratch (device globals — no allocation allowed)
__device__ __align__(16) __half g_lph[(size_t)BB * TT * ROWH];  // ~34 MB fp16 u-values
__device__ float g_lz[TT * BB];    // per-row log-sum-exp residual
__device__ float g_ps[BB];

__device__ __forceinline__ void cpasync16(void* smem_dst, const void* gsrc) {
    uint32_t sa = (uint32_t)__cvta_generic_to_shared(smem_dst);
    asm volatile("cp.async.cg.shared.global [%0], [%1], 16;\n" :: "r"(sa), "l"(gsrc));
}

// ---------------------------------------------------------------------------
// Kernel 1: per (t,b) row with t < act_len(b): softmax stats; store
// UNNORMALIZED probs u[c]=exp(a[c]-rowmax) as fp16 + fp32 lz residual.
// Rows t >= act_len are never consumed -> whole warp exits before reading.
// ---------------------------------------------------------------------------
__global__ void k_logprobs(const float* __restrict__ acts,
                           const int*   __restrict__ labels,
                           const int*   __restrict__ act_lens) {
    int gw   = (blockIdx.x * blockDim.x + threadIdx.x) >> 5;   // row id = t*BB + b
    int lane = threadIdx.x & 31;
    if (gw >= TT * BB) return;

    int b = gw & (BB - 1);
    int t = gw >> 7;
    if (t >= act_lens[b]) return;             // dead row: skip entirely

    const float* row = acts + (size_t)gw * VV;
    const float4* r4 = (const float4*)row;

    float4 a0 = r4[lane];
    float4 a1 = r4[lane + 32];
    float4 a2 = r4[lane + 64];
    float4 a3 = r4[lane + 96];

    float m = fmaxf(fmaxf(fmaxf(a0.x, a0.y), fmaxf(a0.z, a0.w)),
                    fmaxf(fmaxf(a1.x, a1.y), fmaxf(a1.z, a1.w)));
    m = fmaxf(m, fmaxf(fmaxf(a2.x, a2.y), fmaxf(a2.z, a2.w)));
    m = fmaxf(m, fmaxf(fmaxf(a3.x, a3.y), fmaxf(a3.z, a3.w)));
    #pragma unroll
    for (int o = 16; o; o >>= 1) m = fmaxf(m, __shfl_xor_sync(0xFFFFFFFFu, m, o));

    float s = __expf(a0.x - m) + __expf(a0.y - m) + __expf(a0.z - m) + __expf(a0.w - m)
            + __expf(a1.x - m) + __expf(a1.y - m) + __expf(a1.z - m) + __expf(a1.w - m)
            + __expf(a2.x - m) + __expf(a2.y - m) + __expf(a2.z - m) + __expf(a2.w - m)
            + __expf(a3.x - m) + __expf(a3.y - m) + __expf(a3.z - m) + __expf(a3.w - m);
    #pragma unroll
    for (int o = 16; o; o >>= 1) s += __shfl_xor_sync(0xFFFFFFFFu, s, o);

    const int* lab = labels + b * LMAX;
    __half* dst = g_lph + ((size_t)b * TT + t) * ROWH;
    #pragma unroll
    for (int j = lane; j < LMAX; j += 32) {
        int c = lab[j];                              // in [1, VV)
        dst[1 + j] = __float2half(__expf(row[c] - m));   // L1 hit
    }
    if (lane == 0) {
        dst[0] = __float2half(__expf(row[0] - m));   // blank
        g_lz[gw] = __logf(s);                        // residual normalizer
    }
}

// ---------------------------------------------------------------------------
// Kernel 2: per-sample alpha scan in SCALED LINEAR domain (no MUFU in loop).
// Pair p owns s=2p (blank) and s=2p+1 (label):
//   ae' = (ae + ao[p-1]) * u_blank
//   ao' = (ao + ae + [allow2]*ao[p-1]) * u_lab[p]
// Lattice truncated at true label length Lb (p >= Lb identically 0).
// Wavefront halo: KSTEP=12 barrier-free steps per phase (1 shfl_up/step);
// 7 warps, lanes 0..11 decaying halo, lanes 12..31 own PWARP=20 pairs.
// Per-phase power-of-2 renorm pins block max to 2^TEXP via ONE
// __reduce_max_sync (positive floats are uint-monotone) instead of a 5-shfl
// tree. Growth bound 3^12 = 2^19 < headroom (2^110 vs 2^127).
// wred double-buffered by phase parity (two-barrier separation).
// log P = log(ae_end + ao_end-1) + ln2*Ce - sum_t lz(t).
// ---------------------------------------------------------------------------
__global__ __launch_bounds__(NTHR, 1)
void k_alpha(const int* __restrict__ labels,
             const int* __restrict__ act_lens,
             const int* __restrict__ label_lens) {
    __shared__ __align__(16) __half tile[2][CHUNK][ROWH];  // 13 KB
    __shared__ float xae[2][132];
    __shared__ float xao[2][132];
    __shared__ float wred[2][NWARP];  // renorm max, double-buffered by parity
    __shared__ int   lab[LMAX];

    int b   = blockIdx.x;
    int tid = threadIdx.x;
    int w   = tid >> 5;
    int l   = tid & 31;
    int p   = PWARP * w - KSTEP + l;          // pair index in [-12, 139]

    if (tid < LMAX) lab[tid] = labels[b * LMAX + tid];
    if (tid < 132) { xae[0][tid] = 0.0f; xao[0][tid] = 0.0f; }
    int len = act_lens[b];
    int Lb  = label_lens[b];                  // true label length, [64, 128]
    const __half* my = g_lph + (size_t)b * TT * ROWH;
    __syncthreads();
    if (tid == 0) {
        xae[0][0] = __half2float(my[0]);
        xao[0][0] = __half2float(my[1]);
    }

    bool haveP  = (p >= 0 && p <= 128);
    bool okO    = (p >= 0 && p < Lb);         // active odd positions only
    bool ownA   = (l >= KSTEP) && (p >= 0) && (p <= 128);
    bool ownO   = (l >= KSTEP) && (p >= 0) && (p <= 127);
    float allow2f = ((p >= 1 && p <= 127) ? (lab[p] != lab[p - 1]) : false) ? 1.0f : 0.0f;

    // ---- cp.async chunk prefetcher (16B = 8 halves; 17 words/row) ----
    const int NWD = CHUNK * (ROWH / 8);       // 408 words per chunk
    auto prefetch = [&](int t0, int bf) {
        for (int wd = tid; wd < NWD; wd += NTHR) {
            int tt = wd / (ROWH / 8);
            int q  = wd - tt * (ROWH / 8);
            int t  = t0 + tt;
            if (t < TT)
                cpasync16(&tile[bf][tt][q * 8], my + (size_t)t * ROWH + q * 8);
        }
        asm volatile("cp.async.commit_group;\n");
    };

    prefetch(1, 0);
    if (1 + CHUNK < len) prefetch(1 + CHUNK, 1);
    __syncthreads();

    int   par   = 0, buf = 0;
    int   Ce    = 0;         // accumulated renorm exponent: true = stored * 2^Ce
    int   pend  = 0;         // exponent of last phase's max (2^pend >= mx)
    float scale = __int_as_float((127 + TEXP) << 23);   // 2^(TEXP-pend), pend=0

    for (int cs = 1; cs < len; cs += CHUNK, buf ^= 1) {
        bool more = (cs + CHUNK) < len;
        if (more) asm volatile("cp.async.wait_group 1;\n");
        else      asm volatile("cp.async.wait_group 0;\n");
        __syncthreads();                      // tile[buf] ready

        int ce = more ? (cs + CHUNK) : len;
        for (int base = cs; base < ce; base += KSTEP) {
            float a_e = haveP ? xae[par][p] * scale : 0.0f;
            float a_o = okO   ? xao[par][p] * scale : 0.0f;
            Ce += pend - TEXP;               // matches scale = 2^(TEXP-pend)

            #pragma unroll
            for (int k = 0; k < KSTEP; k++) {
                if (base + k >= ce) break;    // uniform across CTA
                int tt = base + k - cs;
                float ub = __half2float(tile[buf][tt][0]);
                float ul = okO ? __half2float(tile[buf][tt][1 + p]) : 0.0f;
                float aim1 = __shfl_up_sync(0xFFFFFFFFu, a_o, 1);
                if (l == 0) aim1 = 0.0f;
                float nae = (a_e + aim1) * ub;
                float nao = (a_o + a_e + allow2f * aim1) * ul;
                a_e = nae;
                a_o = nao;
            }

            // per-warp max for renorm: one redux instead of 5-shfl tree
            // (halo lanes only underestimate; p>128 spill lanes hold plausible
            // magnitudes -> max can only be overestimated by <1 step: safe)
            float v = fmaxf(a_e, a_o);
            unsigned mv = __reduce_max_sync(0xFFFFFFFFu, __float_as_uint(v));
            if (l == 0) wred[par][w] = __uint_as_float(mv);

            if (ownA) xae[par ^ 1][p] = a_e;
            if (ownO) xao[par ^ 1][p] = a_o;
            __syncthreads();

            // uniform rescale-to-2^TEXP factor for next phase
            float mx = fmaxf(fmaxf(fmaxf(wred[par][0], wred[par][1]),
                                   fmaxf(wred[par][2], wred[par][3])),
                             fmaxf(fmaxf(wred[par][4], wred[par][5]), wred[par][6]));
            par ^= 1;
            pend  = (__float_as_int(mx) >> 23) - 126;           // 2^pend >= mx
            scale = __int_as_float((127 + TEXP - pend) << 23);  // 2^(TEXP-pend)
        }

        int nc = cs + 2 * CHUNK;
        if (nc < len) prefetch(nc, buf);
    }

    // ---- sum of per-row normalizers lz over t < len ----
    float slz = 0.0f;
    for (int t = tid; t < len; t += NTHR) slz += g_lz[t * BB + b];
    #pragma unroll
    for (int o = 16; o; o >>= 1) slz += __shfl_xor_sync(0xFFFFFFFFu, slz, o);
    __syncthreads();
    if (l == 0) wred[0][w] = slz;
    __syncthreads();

    if (tid == 0) {
        float SLZ = wred[0][0] + wred[0][1] + wred[0][2] + wred[0][3]
                  + wred[0][4] + wred[0][5] + wred[0][6];
        float af = xae[par][Lb] + xao[par][Lb - 1];   // end = 2L -> ae[L], ao[L-1]
        g_ps[b] = -(__logf(af) + (float)Ce * LN2F - SLZ);
    }
}

// ---------------------------------------------------------------------------
// Kernel 3: deterministic mean over B=128 per-sample losses.
// ---------------------------------------------------------------------------
__global__ void k_final(float* __restrict__ out) {
    __shared__ float sh[4];
    int tid = threadIdx.x;                   // 128 threads
    float v = g_ps[tid];
    #pragma unroll
    for (int o = 16; o; o >>= 1) v += __shfl_xor_sync(0xFFFFFFFFu, v, o);
    if ((tid & 31) == 0) sh[tid >> 5] = v;
    __syncthreads();
    if (tid == 0) out[0] = (sh[0] + sh[1] + sh[2] + sh[3]) * (1.0f / (float)BB);
}

extern "C" void kernel_launch(void* const* d_in, const int* in_sizes, int n_in,
                              void* d_out, int out_size) {
    const float* acts       = (const float*)d_in[0];
    const int*   labels     = (const int*)d_in[1];
    const int*   act_lens   = (const int*)d_in[2];
    const int*   label_lens = (const int*)d_in[3];
    (void)in_sizes; (void)n_in; (void)out_size;

    k_logprobs<<<(TT * BB) / 8, 256>>>(acts, labels, act_lens);
    k_alpha<<<BB, NTHR>>>(labels, act_lens, label_lens);
    k_final<<<1, 128>>>((float*)d_out);
}